// round 15
// baseline (speedup 1.0000x reference)
#include <cuda_runtime.h>

#define BB 256
#define DD 1024
#define LOG2E 1.4426950408889634f
#define NSPLIT 6

// scratch: six split-K partial buffers for Q,K,V (3 MB each, ~19 MB total)
__device__ float g_P[NSPLIT * 3 * BB * DD];

__device__ __forceinline__ float ex2f(float x) {
    float y; asm("ex2.approx.ftz.f32 %0, %1;" : "=f"(y) : "f"(x)); return y;
}
__device__ __forceinline__ unsigned long long pk2(float lo, float hi) {
    unsigned long long r; asm("mov.b64 %0, {%1,%2};" : "=l"(r) : "f"(lo), "f"(hi)); return r;
}
__device__ __forceinline__ void upk2(unsigned long long v, float &lo, float &hi) {
    asm("mov.b64 {%0,%1}, %2;" : "=f"(lo), "=f"(hi) : "l"(v));
}
__device__ __forceinline__ unsigned long long ffma2(unsigned long long a, unsigned long long b, unsigned long long c) {
    unsigned long long d;
    asm("fma.rn.f32x2 %0, %1, %2, %3;" : "=l"(d) : "l"(a), "l"(b), "l"(c));
    return d;
}

// ---------------------------------------------------------------------------
// Kernel 1: QKV partial GEMMs, split-K=6 (176x4 + 160x2).
// Tile 128(m) x 128(n) x 16(k), 256 threads, 8m x 8n per thread.
// Accumulators packed over m: ffma2(a_pair, b_dup) -> A read as natural
// (m0,m1) pairs from smem, B stored PRE-DUPLICATED (w,w). Inner loop is
// 6x LDS.128 + 32x FFMA2, ZERO packing MOVs.
// grid = (2, 8, 18) = 288 blocks, 2 blocks/SM, one wave.
// ---------------------------------------------------------------------------
#define TM 128
#define TN 128
#define TK 16
#define GTH 256

__global__ __launch_bounds__(GTH, 2) void gemm_qkv_kernel(
    const float* __restrict__ x,
    const float* __restrict__ Wq,
    const float* __restrict__ Wk,
    const float* __restrict__ Wv)
{
    const int z  = blockIdx.z;
    const int g  = z % 3;        // 0=Q, 1=K, 2=V
    const int ks = z / 3;        // k-split index 0..5
    const float* W = (g == 0) ? Wq : (g == 1) ? Wk : Wv;
    float* out = g_P + ks * (3 * BB * DD) + g * (BB * DD);
    const int k0 = (ks < 4) ? ks * 176 : 704 + (ks - 4) * 160;
    const int NT = (ks < 4) ? 11 : 10;   // k-tiles of 16

    __shared__ __align__(16) float  xs[2][TK][TM];   // 16KB, plain A
    __shared__ __align__(16) float2 ws[2][TK][TN];   // 32KB, duplicated (w,w)

    const int t  = threadIdx.x;
    const int m0 = blockIdx.x * TM;
    const int n0 = blockIdx.y * TN;

    // loaders: 256 threads fill 128 rows x 16 k (8 consecutive k per thread)
    const int lr  = t & 127;           // row (m for x, n for W)
    const int lk0 = (t >> 7) * 8;      // 0 or 8

    // compute map: 16(tx,n) x 16(ty,m)
    const int tx = t & 15;
    const int ty = t >> 4;

    // acc[p][n]: p = m-pair (0: m=ty*4+0/1, 1: ty*4+2/3, 2: 64+ty*4+0/1, 3: 64+ty*4+2/3)
    unsigned long long acc[4][8];
#pragma unroll
    for (int i = 0; i < 4; i++)
#pragma unroll
        for (int j = 0; j < 8; j++) acc[i][j] = pk2(0.f, 0.f);

    const float* xp = &x[(m0 + lr) * DD + k0 + lk0];
    const float* wp = &W[(n0 + lr) * DD + k0 + lk0];

    float4 ax0, ax1, aw0, aw1;
    ax0 = *(const float4*)(xp);  ax1 = *(const float4*)(xp + 4);
    aw0 = *(const float4*)(wp);  aw1 = *(const float4*)(wp + 4);

    int buf = 0;
#pragma unroll
    for (int j = 0; j < 4; j++) {
        xs[0][lk0 + j][lr]     = ((const float*)&ax0)[j];
        xs[0][lk0 + 4 + j][lr] = ((const float*)&ax1)[j];
        ws[0][lk0 + j][lr]     = make_float2(((const float*)&aw0)[j], ((const float*)&aw0)[j]);
        ws[0][lk0 + 4 + j][lr] = make_float2(((const float*)&aw1)[j], ((const float*)&aw1)[j]);
    }
    __syncthreads();

    for (int kt = 0; kt < NT; kt++) {
        if (kt + 1 < NT) {
            const float* px = xp + (kt + 1) * TK;
            const float* pw = wp + (kt + 1) * TK;
            ax0 = *(const float4*)(px);  ax1 = *(const float4*)(px + 4);
            aw0 = *(const float4*)(pw);  aw1 = *(const float4*)(pw + 4);
        }
#pragma unroll
        for (int kk = 0; kk < TK; kk++) {
            // A: natural (m_even, m_odd) pairs, warp-broadcast
            ulonglong2 a01 = *(const ulonglong2*)&xs[buf][kk][ty * 4];
            ulonglong2 a23 = *(const ulonglong2*)&xs[buf][kk][64 + ty * 4];
            // B: duplicated scalars (w,w)
            ulonglong2 b01 = *(const ulonglong2*)&ws[buf][kk][tx * 4];
            ulonglong2 b23 = *(const ulonglong2*)&ws[buf][kk][tx * 4 + 2];
            ulonglong2 b45 = *(const ulonglong2*)&ws[buf][kk][64 + tx * 4];
            ulonglong2 b67 = *(const ulonglong2*)&ws[buf][kk][64 + tx * 4 + 2];

            acc[0][0] = ffma2(a01.x, b01.x, acc[0][0]);
            acc[0][1] = ffma2(a01.x, b01.y, acc[0][1]);
            acc[0][2] = ffma2(a01.x, b23.x, acc[0][2]);
            acc[0][3] = ffma2(a01.x, b23.y, acc[0][3]);
            acc[0][4] = ffma2(a01.x, b45.x, acc[0][4]);
            acc[0][5] = ffma2(a01.x, b45.y, acc[0][5]);
            acc[0][6] = ffma2(a01.x, b67.x, acc[0][6]);
            acc[0][7] = ffma2(a01.x, b67.y, acc[0][7]);

            acc[1][0] = ffma2(a01.y, b01.x, acc[1][0]);
            acc[1][1] = ffma2(a01.y, b01.y, acc[1][1]);
            acc[1][2] = ffma2(a01.y, b23.x, acc[1][2]);
            acc[1][3] = ffma2(a01.y, b23.y, acc[1][3]);
            acc[1][4] = ffma2(a01.y, b45.x, acc[1][4]);
            acc[1][5] = ffma2(a01.y, b45.y, acc[1][5]);
            acc[1][6] = ffma2(a01.y, b67.x, acc[1][6]);
            acc[1][7] = ffma2(a01.y, b67.y, acc[1][7]);

            acc[2][0] = ffma2(a23.x, b01.x, acc[2][0]);
            acc[2][1] = ffma2(a23.x, b01.y, acc[2][1]);
            acc[2][2] = ffma2(a23.x, b23.x, acc[2][2]);
            acc[2][3] = ffma2(a23.x, b23.y, acc[2][3]);
            acc[2][4] = ffma2(a23.x, b45.x, acc[2][4]);
            acc[2][5] = ffma2(a23.x, b45.y, acc[2][5]);
            acc[2][6] = ffma2(a23.x, b67.x, acc[2][6]);
            acc[2][7] = ffma2(a23.x, b67.y, acc[2][7]);

            acc[3][0] = ffma2(a23.y, b01.x, acc[3][0]);
            acc[3][1] = ffma2(a23.y, b01.y, acc[3][1]);
            acc[3][2] = ffma2(a23.y, b23.x, acc[3][2]);
            acc[3][3] = ffma2(a23.y, b23.y, acc[3][3]);
            acc[3][4] = ffma2(a23.y, b45.x, acc[3][4]);
            acc[3][5] = ffma2(a23.y, b45.y, acc[3][5]);
            acc[3][6] = ffma2(a23.y, b67.x, acc[3][6]);
            acc[3][7] = ffma2(a23.y, b67.y, acc[3][7]);
        }
        if (kt + 1 < NT) {
            __syncthreads();
            buf ^= 1;
#pragma unroll
            for (int j = 0; j < 4; j++) {
                xs[buf][lk0 + j][lr]     = ((const float*)&ax0)[j];
                xs[buf][lk0 + 4 + j][lr] = ((const float*)&ax1)[j];
                ws[buf][lk0 + j][lr]     = make_float2(((const float*)&aw0)[j], ((const float*)&aw0)[j]);
                ws[buf][lk0 + 4 + j][lr] = make_float2(((const float*)&aw1)[j], ((const float*)&aw1)[j]);
            }
            __syncthreads();
        }
    }

    // epilogue: unpack m-pairs, write two rows per pair, 4 STG.128 each
#pragma unroll
    for (int p = 0; p < 4; p++) {
        const int row = m0 + ((p < 2) ? (ty * 4 + 2 * p) : (64 + ty * 4 + 2 * (p - 2)));
        float lo[8], hi[8];
#pragma unroll
        for (int n = 0; n < 8; n++) upk2(acc[p][n], lo[n], hi[n]);
        float4 o;
        o.x = lo[0]; o.y = lo[1]; o.z = lo[2]; o.w = lo[3];
        *(float4*)&out[row * DD + n0 + tx * 4] = o;
        o.x = lo[4]; o.y = lo[5]; o.z = lo[6]; o.w = lo[7];
        *(float4*)&out[row * DD + n0 + 64 + tx * 4] = o;
        o.x = hi[0]; o.y = hi[1]; o.z = hi[2]; o.w = hi[3];
        *(float4*)&out[(row + 1) * DD + n0 + tx * 4] = o;
        o.x = hi[4]; o.y = hi[5]; o.z = hi[6]; o.w = hi[7];
        *(float4*)&out[(row + 1) * DD + n0 + 64 + tx * 4] = o;
    }
}

// ---------------------------------------------------------------------------
// Kernel 2: per-(b,i) scalar-softmax attention + residual.
// Fuses the 6-way split-K reduction and QKV bias adds into the load phase.
// grid = 1024 blocks (b x i-quarter), 256 threads; inner loop at MUFU roofline.
// ---------------------------------------------------------------------------
__global__ __launch_bounds__(256) void attn_kernel(
    const float* __restrict__ x,
    const float* __restrict__ scale_p,
    const float* __restrict__ bq,
    const float* __restrict__ bk,
    const float* __restrict__ bv,
    float* __restrict__ out)
{
    const int b     = blockIdx.x >> 2;
    const int ibase = (blockIdx.x & 3) << 8;
    const int t     = threadIdx.x;

    __shared__ float2 kv[DD];
    __shared__ float redmx[8], redmn[8];

    const int koff = BB * DD + b * DD;
    const int voff = 2 * BB * DD + b * DD;

    float mx = -1e30f, mn = 1e30f;
#pragma unroll
    for (int j = t; j < DD; j += 256) {
        float kx = bk[j];
        float vy = bv[j];
#pragma unroll
        for (int s = 0; s < NSPLIT; s++) {
            kx += g_P[s * (3 * BB * DD) + koff + j];
            vy += g_P[s * (3 * BB * DD) + voff + j];
        }
        kv[j] = make_float2(kx, vy);
        mx = fmaxf(mx, kx);
        mn = fminf(mn, kx);
    }
#pragma unroll
    for (int o = 16; o > 0; o >>= 1) {
        mx = fmaxf(mx, __shfl_xor_sync(0xFFFFFFFFu, mx, o));
        mn = fminf(mn, __shfl_xor_sync(0xFFFFFFFFu, mn, o));
    }
    if ((t & 31) == 0) { redmx[t >> 5] = mx; redmn[t >> 5] = mn; }
    __syncthreads();
    mx = redmx[0]; mn = redmn[0];
#pragma unroll
    for (int w = 1; w < 8; w++) { mx = fmaxf(mx, redmx[w]); mn = fminf(mn, redmn[w]); }

    const int   i   = ibase + t;
    const int   qi  = b * DD + i;
    float q = bq[i];
#pragma unroll
    for (int s = 0; s < NSPLIT; s++) q += g_P[s * (3 * BB * DD) + qi];

    const float cs  = LOG2E / scale_p[0];
    const float c2  = q * cs;                              // Q scaled into log2 domain
    const float m2  = (c2 >= 0.f) ? c2 * mx : c2 * mn;     // row max in log2 domain
    const float nm2 = -m2;

    float s  = 0.f;
    float dn = 0.f;
#pragma unroll 8
    for (int j = 0; j < DD; j++) {
        float2 kvj = kv[j];                        // broadcast LDS.64
        float  e   = ex2f(__fmaf_rn(c2, kvj.x, nm2));
        s  += e;
        dn  = __fmaf_rn(e, kvj.y, dn);
    }

    out[b * DD + i] = dn / s + x[b * DD + i];
}

// ---------------------------------------------------------------------------
// Kernel 3: in-place RMSNorm over each row of out. grid = 256, 256 threads.
// ---------------------------------------------------------------------------
__global__ __launch_bounds__(256) void rmsnorm_kernel(
    float* __restrict__ out, const float* __restrict__ nw)
{
    const int b = blockIdx.x;
    const int t = threadIdx.x;
    __shared__ float red[8];

    float4 h = *(const float4*)&out[b * DD + t * 4];
    float local = h.x * h.x + h.y * h.y + h.z * h.z + h.w * h.w;
#pragma unroll
    for (int o = 16; o > 0; o >>= 1) local += __shfl_xor_sync(0xFFFFFFFFu, local, o);
    if ((t & 31) == 0) red[t >> 5] = local;
    __syncthreads();
    float tot = 0.f;
#pragma unroll
    for (int w = 0; w < 8; w++) tot += red[w];

    float r = rsqrtf(tot * (1.0f / DD) + 1e-6f);
    float4 w4 = *(const float4*)&nw[t * 4];
    float4 o;
    o.x = h.x * r * w4.x;
    o.y = h.y * r * w4.y;
    o.z = h.z * r * w4.z;
    o.w = h.w * r * w4.w;
    *(float4*)&out[b * DD + t * 4] = o;
}

extern "C" void kernel_launch(void* const* d_in, const int* in_sizes, int n_in,
                              void* d_out, int out_size)
{
    const float* x     = (const float*)d_in[0];
    const float* Wq    = (const float*)d_in[1];
    const float* bq    = (const float*)d_in[2];
    const float* Wk    = (const float*)d_in[3];
    const float* bk    = (const float*)d_in[4];
    const float* Wv    = (const float*)d_in[5];
    const float* bv    = (const float*)d_in[6];
    const float* scale = (const float*)d_in[7];
    const float* nw    = (const float*)d_in[8];
    float* out = (float*)d_out;

    dim3 ggrid(BB / TM, DD / TN, 3 * NSPLIT);   // z = ks*3 + gemm_id
    gemm_qkv_kernel<<<ggrid, GTH>>>(x, Wq, Wk, Wv);
    attn_kernel<<<BB * 4, 256>>>(x, scale, bq, bk, bv, out);
    rmsnorm_kernel<<<BB, 256>>>(out, nw);
}

// round 17
// speedup vs baseline: 1.9340x; 1.9340x over previous
#include <cuda_runtime.h>
#include <cstdint>

#define BB 256
#define DD 1024
#define LOG2E 1.4426950408889634f
#define NSPLIT 3

// scratch: three split-K partial buffers for Q,K,V (3 MB each, ~9.4 MB total)
__device__ float g_P[NSPLIT * 3 * BB * DD];

__device__ __forceinline__ float ex2f(float x) {
    float y; asm("ex2.approx.ftz.f32 %0, %1;" : "=f"(y) : "f"(x)); return y;
}
__device__ __forceinline__ unsigned long long pk2(float lo, float hi) {
    unsigned long long r; asm("mov.b64 %0, {%1,%2};" : "=l"(r) : "f"(lo), "f"(hi)); return r;
}
__device__ __forceinline__ void upk2(unsigned long long v, float &lo, float &hi) {
    asm("mov.b64 {%0,%1}, %2;" : "=f"(lo), "=f"(hi) : "l"(v));
}
__device__ __forceinline__ unsigned long long ffma2(unsigned long long a, unsigned long long b, unsigned long long c) {
    unsigned long long d;
    asm("fma.rn.f32x2 %0, %1, %2, %3;" : "=l"(d) : "l"(a), "l"(b), "l"(c));
    return d;
}
__device__ __forceinline__ void cpa16(unsigned int dst, const void* src) {
    asm volatile("cp.async.cg.shared.global [%0], [%1], 16;" :: "r"(dst), "l"(src));
}
__device__ __forceinline__ void cpa_commit() {
    asm volatile("cp.async.commit_group;" ::: "memory");
}
__device__ __forceinline__ void cpa_wait0() {
    asm volatile("cp.async.wait_group 0;" ::: "memory");
}

// ---------------------------------------------------------------------------
// Kernel 1: QKV partial GEMMs, split-K=3 (352/352/320).
// Tile 128(m) x 128(n) x 16(k), 512 threads, 8m x 4n outputs per thread.
// K-PARITY-PACKED accumulators: each f32x2 acc holds (even-k sum, odd-k sum)
// of ONE output -> both A and B are read as natural consecutive-k pairs:
// NO smem duplication, NO packing MOVs. Final = lo + hi.
// A: [m][k] pad-20 rows, loaded by cp.async (transpose-free), read as
//    broadcast LDS.128 (4k = 2 pairs). B: LDG+STS.64 transpose into
//    [k2][n] float2, read conflict-free LDS.64.
// grid = (2, 8, 9) = 144 blocks = one/SM, 16 warps/SM.
// ---------------------------------------------------------------------------
#define TM 128
#define TN 128
#define TK 16
#define APAD 20
#define GTH 512

__global__ __launch_bounds__(GTH, 1) void gemm_qkv_kernel(
    const float* __restrict__ x,
    const float* __restrict__ Wq,
    const float* __restrict__ Wk,
    const float* __restrict__ Wv)
{
    const int z  = blockIdx.z;
    const int g  = z % 3;        // 0=Q, 1=K, 2=V
    const int ks = z / 3;        // k-split index 0..2
    const float* W = (g == 0) ? Wq : (g == 1) ? Wk : Wv;
    float* out = g_P + ks * (3 * BB * DD) + g * (BB * DD);
    const int k0 = ks * 352;
    const int NT = (ks < 2) ? 22 : 20;   // k-tiles of 16

    __shared__ __align__(16) float  xs[2][TM][APAD];    // A row-major, 20.5KB
    __shared__ __align__(16) float2 wsp[2][TK / 2][TN]; // B k2-major, 16KB

    const int t  = threadIdx.x;
    const int m0 = blockIdx.x * TM;
    const int n0 = blockIdx.y * TN;

    // loaders: 512 threads, 128 rows x 4 k-chunk each
    const int lr = t & 127;            // row (m for x, n for W)
    const int lk = (t >> 7) * 4;       // 0,4,8,12
    const int lk2 = lk >> 1;           // 0,2,4,6 (k2 index of first pair)

    // compute map: tx = lane n-group, ty = warp m-group
    const int tx = t & 31;             // n = tx + 32c, c=0..3
    const int ty = t >> 5;             // m = ty + 16p, p=0..7 (uniform per warp)

    unsigned long long acc[8][4];
#pragma unroll
    for (int i = 0; i < 8; i++)
#pragma unroll
        for (int j = 0; j < 4; j++) acc[i][j] = pk2(0.f, 0.f);

    const float* xp = &x[(m0 + lr) * DD + k0 + lk];
    const float* wp = &W[(n0 + lr) * DD + k0 + lk];

    const unsigned int xs0 = (unsigned int)__cvta_generic_to_shared(&xs[0][lr][lk]);
    const unsigned int xs1 = (unsigned int)__cvta_generic_to_shared(&xs[1][lr][lk]);

    // prologue: tile 0
    cpa16(xs0, xp);
    cpa_commit();
    float4 bw = *(const float4*)wp;
    wsp[0][lk2][lr]     = make_float2(bw.x, bw.y);
    wsp[0][lk2 + 1][lr] = make_float2(bw.z, bw.w);

    int buf = 0;
    for (int kt = 0; kt < NT; kt++) {
        if (kt + 1 < NT) bw = *(const float4*)(wp + (kt + 1) * TK);

        cpa_wait0();
        __syncthreads();          // tile kt (A async + B STS) visible to all

        if (kt + 1 < NT) {        // safe: all warps passed the barrier above
            cpa16(buf ? xs0 : xs1, xp + (kt + 1) * TK);
            cpa_commit();
        }

#pragma unroll
        for (int j = 0; j < TK / 4; j++) {      // 4 k per step = 2 k2
            ulonglong2 a4[8];
#pragma unroll
            for (int p = 0; p < 8; p++)         // broadcast LDS.128
                a4[p] = *(const ulonglong2*)&xs[buf][ty + 16 * p][4 * j];
#pragma unroll
            for (int sub = 0; sub < 2; sub++) {
                const int k2 = 2 * j + sub;
                unsigned long long b0 = *(const unsigned long long*)&wsp[buf][k2][tx];
                unsigned long long b1 = *(const unsigned long long*)&wsp[buf][k2][tx + 32];
                unsigned long long b2 = *(const unsigned long long*)&wsp[buf][k2][tx + 64];
                unsigned long long b3 = *(const unsigned long long*)&wsp[buf][k2][tx + 96];
#pragma unroll
                for (int p = 0; p < 8; p++) {
                    const unsigned long long ap = sub ? a4[p].y : a4[p].x;
                    acc[p][0] = ffma2(ap, b0, acc[p][0]);
                    acc[p][1] = ffma2(ap, b1, acc[p][1]);
                    acc[p][2] = ffma2(ap, b2, acc[p][2]);
                    acc[p][3] = ffma2(ap, b3, acc[p][3]);
                }
            }
        }

        if (kt + 1 < NT) {        // write B tile kt+1 into the other buffer
            wsp[buf ^ 1][lk2][lr]     = make_float2(bw.x, bw.y);
            wsp[buf ^ 1][lk2 + 1][lr] = make_float2(bw.z, bw.w);
        }
        buf ^= 1;
    }

    // epilogue: final value = even-k sum + odd-k sum
#pragma unroll
    for (int p = 0; p < 8; p++) {
        const int row = m0 + ty + 16 * p;
#pragma unroll
        for (int c = 0; c < 4; c++) {
            float lo, hi;
            upk2(acc[p][c], lo, hi);
            out[row * DD + n0 + tx + 32 * c] = lo + hi;
        }
    }
}

// ---------------------------------------------------------------------------
// Kernel 2: per-(b,i) scalar-softmax attention + residual.
// Fuses the 3-way split-K reduction and QKV bias adds into the load phase.
// grid = 1024 blocks (b x i-quarter), 256 threads; inner loop at MUFU roofline.
// ---------------------------------------------------------------------------
__global__ __launch_bounds__(256) void attn_kernel(
    const float* __restrict__ x,
    const float* __restrict__ scale_p,
    const float* __restrict__ bq,
    const float* __restrict__ bk,
    const float* __restrict__ bv,
    float* __restrict__ out)
{
    const int b     = blockIdx.x >> 2;
    const int ibase = (blockIdx.x & 3) << 8;
    const int t     = threadIdx.x;

    __shared__ float2 kv[DD];
    __shared__ float redmx[8], redmn[8];

    const int koff = BB * DD + b * DD;
    const int voff = 2 * BB * DD + b * DD;

    float mx = -1e30f, mn = 1e30f;
#pragma unroll
    for (int j = t; j < DD; j += 256) {
        float kx = bk[j];
        float vy = bv[j];
#pragma unroll
        for (int s = 0; s < NSPLIT; s++) {
            kx += g_P[s * (3 * BB * DD) + koff + j];
            vy += g_P[s * (3 * BB * DD) + voff + j];
        }
        kv[j] = make_float2(kx, vy);
        mx = fmaxf(mx, kx);
        mn = fminf(mn, kx);
    }
#pragma unroll
    for (int o = 16; o > 0; o >>= 1) {
        mx = fmaxf(mx, __shfl_xor_sync(0xFFFFFFFFu, mx, o));
        mn = fminf(mn, __shfl_xor_sync(0xFFFFFFFFu, mn, o));
    }
    if ((t & 31) == 0) { redmx[t >> 5] = mx; redmn[t >> 5] = mn; }
    __syncthreads();
    mx = redmx[0]; mn = redmn[0];
#pragma unroll
    for (int w = 1; w < 8; w++) { mx = fmaxf(mx, redmx[w]); mn = fminf(mn, redmn[w]); }

    const int   i   = ibase + t;
    const int   qi  = b * DD + i;
    float q = bq[i];
#pragma unroll
    for (int s = 0; s < NSPLIT; s++) q += g_P[s * (3 * BB * DD) + qi];

    const float cs  = LOG2E / scale_p[0];
    const float c2  = q * cs;                              // Q scaled into log2 domain
    const float m2  = (c2 >= 0.f) ? c2 * mx : c2 * mn;     // row max in log2 domain
    const float nm2 = -m2;

    float s  = 0.f;
    float dn = 0.f;
#pragma unroll 8
    for (int j = 0; j < DD; j++) {
        float2 kvj = kv[j];                        // broadcast LDS.64
        float  e   = ex2f(__fmaf_rn(c2, kvj.x, nm2));
        s  += e;
        dn  = __fmaf_rn(e, kvj.y, dn);
    }

    out[b * DD + i] = dn / s + x[b * DD + i];
}

// ---------------------------------------------------------------------------
// Kernel 3: in-place RMSNorm over each row of out. grid = 256, 256 threads.
// ---------------------------------------------------------------------------
__global__ __launch_bounds__(256) void rmsnorm_kernel(
    float* __restrict__ out, const float* __restrict__ nw)
{
    const int b = blockIdx.x;
    const int t = threadIdx.x;
    __shared__ float red[8];

    float4 h = *(const float4*)&out[b * DD + t * 4];
    float local = h.x * h.x + h.y * h.y + h.z * h.z + h.w * h.w;
#pragma unroll
    for (int o = 16; o > 0; o >>= 1) local += __shfl_xor_sync(0xFFFFFFFFu, local, o);
    if ((t & 31) == 0) red[t >> 5] = local;
    __syncthreads();
    float tot = 0.f;
#pragma unroll
    for (int w = 0; w < 8; w++) tot += red[w];

    float r = rsqrtf(tot * (1.0f / DD) + 1e-6f);
    float4 w4 = *(const float4*)&nw[t * 4];
    float4 o;
    o.x = h.x * r * w4.x;
    o.y = h.y * r * w4.y;
    o.z = h.z * r * w4.z;
    o.w = h.w * r * w4.w;
    *(float4*)&out[b * DD + t * 4] = o;
}

extern "C" void kernel_launch(void* const* d_in, const int* in_sizes, int n_in,
                              void* d_out, int out_size)
{
    const float* x     = (const float*)d_in[0];
    const float* Wq    = (const float*)d_in[1];
    const float* bq    = (const float*)d_in[2];
    const float* Wk    = (const float*)d_in[3];
    const float* bk    = (const float*)d_in[4];
    const float* Wv    = (const float*)d_in[5];
    const float* bv    = (const float*)d_in[6];
    const float* scale = (const float*)d_in[7];
    const float* nw    = (const float*)d_in[8];
    float* out = (float*)d_out;

    dim3 ggrid(BB / TM, DD / TN, 3 * NSPLIT);   // z = ks*3 + gemm_id
    gemm_qkv_kernel<<<ggrid, GTH>>>(x, Wq, Wk, Wv);
    attn_kernel<<<BB * 4, 256>>>(x, scale, bq, bk, bv, out);
    rmsnorm_kernel<<<BB, 256>>>(out, nw);
}